// round 13
// baseline (speedup 1.0000x reference)
#include <cuda_runtime.h>

// Problem constants
#define B_DIM 128
#define T_DIM 256
#define D_DIM 32
#define N_DIM 64

// Scratch (device globals: no allocation allowed)
__device__ float g_aBuf[D_DIM * T_DIM * B_DIM];   // [i][t][b] unnormalized alphas
__device__ float g_denBuf[D_DIM * B_DIM];         // [i][b]
__device__ float g_gBuf[B_DIM * D_DIM * N_DIM];   // [b][i][k] g_n (normalized)
__device__ float g_hTBuf[B_DIM * D_DIM * N_DIM];  // [b][i][k] h_T

// ---------------- math helpers ----------------
static __device__ __forceinline__ float tanha(float x) {
    float y;
    asm("tanh.approx.f32 %0, %1;" : "=f"(y) : "f"(x));
    return y;
}
static __device__ __forceinline__ float siga(float x) {
    return fmaf(tanha(0.5f * x), 0.5f, 0.5f);
}
static __device__ __forceinline__ unsigned cvt_tf32(float x) {
    unsigned r;
    asm("cvt.rna.tf32.f32 %0, %1;" : "=r"(r) : "f"(x));
    return r;
}
// m16n8k8 tf32 MMA, C += A*B  (A row-major frag, B col-major frag)
static __device__ __forceinline__ void mma8(float* C,
                                            unsigned a0, unsigned a1,
                                            unsigned a2, unsigned a3,
                                            unsigned b0, unsigned b1) {
    asm("mma.sync.aligned.m16n8k8.row.col.f32.tf32.tf32.f32 "
        "{%0,%1,%2,%3}, {%4,%5,%6,%7}, {%8,%9}, {%0,%1,%2,%3};"
        : "+f"(C[0]), "+f"(C[1]), "+f"(C[2]), "+f"(C[3])
        : "r"(a0), "r"(a1), "r"(a2), "r"(a3), "r"(b0), "r"(b1));
}
#define GBAR(gid) asm volatile("bar.sync %0, 256;" :: "r"((gid) + 1) : "memory")

// ---------------- shared memory layout (float offsets) ----------------
// x: [t][32 b].  h per group: 2 buffers x [16 rows][stride 68] single tf32 floats.
// sp per group: 2 buffers (t&1) x [8 w][16 b].
#define XS   0       // 8192
#define HBF  8192    // 2 groups * 2 * 1088 = 4352
#define SPF  12544   // 2 groups * 2 * 128 = 512
#define INVF 13056   // 2 * 16 = 32
#define SMTOT 13088  // floats -> 52352 bytes

// ===================== Kernel 1: fused LSTM via single-pass TF32 mma.sync =====================
// grid = (32 i, 4 b-chunks), block = 512 = 2 groups x 8 warps; ONE barrier per step.
// Cross-step pipeline: after the barrier for step t, MMAs for step t+1 are issued
// BEFORE the alpha(t) block, so alpha executes entirely in the MMA shadow.
// Group gid handles b rows [16*gid, 16*gid+16) (M=16).
// Warp wg owns k in [8wg, 8wg+8): nt0=k(0..3)x(j,i), nt1=k(0..3)x(f,o),
//                                 nt2=k(4..7)x(j,i), nt3=k(4..7)x(f,o).
// Lane (g=lane>>2, t4=lane&3): C cells = b rows {g, g+8} x k {8wg+t4, 8wg+4+t4} x 4 gates.
__global__ void __launch_bounds__(512, 1)
lstm_kernel(const float* __restrict__ x,
            const float* __restrict__ Uj, const float* __restrict__ Ui_,
            const float* __restrict__ Uf, const float* __restrict__ Uo,
            const float* __restrict__ Wj, const float* __restrict__ Wi_,
            const float* __restrict__ Wf, const float* __restrict__ Wo,
            const float* __restrict__ bj, const float* __restrict__ bi_,
            const float* __restrict__ bf, const float* __restrict__ bo,
            const float* __restrict__ Fa, const float* __restrict__ Fab) {
    extern __shared__ float sm[];
    const int tid  = threadIdx.x;
    const int gid  = tid >> 8;            // group 0/1
    const int wg   = (tid >> 5) & 7;      // warp in group
    const int lane = tid & 31;
    const int g    = lane >> 2;
    const int t4   = lane & 3;
    const int bl   = lane & 15;           // b-row for alpha compute
    const int i    = blockIdx.x;
    const int b0g  = (blockIdx.y << 5) + (gid << 4);

    // ---- cooperative smem init (full CTA) ----
    {
        const int cb0 = blockIdx.y << 5;
        for (int idx = tid; idx < 8192; idx += 512) {
            int tt = idx >> 5, blx = idx & 31;
            sm[XS + idx] = x[((cb0 + blx) * 256 + tt) * 32 + i];
        }
    }

    // ---- stationary B (weight) fragments, tf32 (exact truncation of W) ----
    unsigned Bhi[8][4][2];
    {
        const float* WgP[4] = {Wj, Wi_, Wf, Wo};
#pragma unroll
        for (int kt = 0; kt < 8; kt++)
#pragma unroll
            for (int nt = 0; nt < 4; nt++) {
                int kB = 8 * wg + ((nt >> 1) << 2) + (g >> 1);
                const float* Wp = WgP[((nt & 1) << 1) + (g & 1)];
#pragma unroll
                for (int r = 0; r < 2; r++) {
                    int j = kt * 8 + t4 + 4 * r;
                    Bhi[kt][nt][r] = cvt_tf32(Wp[(j * 32 + i) * 64 + kB]);
                }
            }
    }

    // ---- per-lane constants: 2 k-values x 4 gates ----
    float Uv[2][4], Bv[2][4], fav[2];
    {
        const float* Ug[4] = {Uj, Ui_, Uf, Uo};
        const float* Bg[4] = {bj, bi_, bf, bo};
#pragma unroll
        for (int ka = 0; ka < 2; ka++) {
            int kk = 8 * wg + 4 * ka + t4;
#pragma unroll
            for (int gg = 0; gg < 4; gg++) {
                Uv[ka][gg] = Ug[gg][i * 64 + kk];
                Bv[ka][gg] = Bg[gg][i * 64 + kk];
            }
            fav[ka] = Fa[kk * 32 + i];
        }
    }
    const float FabV = Fab[i];

    // ---- state ----
    float cst[2][2], gacc[2][2], hn[2][2];
#pragma unroll
    for (int ka = 0; ka < 2; ka++)
#pragma unroll
        for (int bh = 0; bh < 2; bh++) {
            cst[ka][bh] = 0.0f; gacc[ka][bh] = 0.0f; hn[ka][bh] = 0.0f;
        }
    float den = 0.0f;  // per-lane, b = bl (redundant across warps)

    __syncthreads();
    int cur = 0;
    const int hbase  = HBF + gid * 2176;
    const int spbase = SPF + gid * 256;
    const int xb0    = (gid << 4) + g;

    // ---- prologue: C for t=0 is bias + x*U only (h starts at 0; MMA skipped) ----
    float C[4][4];
    {
        const float xv0 = sm[XS + xb0];
        const float xv1 = sm[XS + xb0 + 8];
#pragma unroll
        for (int nt = 0; nt < 4; nt++)
#pragma unroll
            for (int r = 0; r < 4; r++) {
                int gate = ((nt & 1) << 1) + (r & 1);
                int ka = nt >> 1;
                C[nt][r] = fmaf((r >> 1) ? xv1 : xv0, Uv[ka][gate], Bv[ka][gate]);
            }
    }

    for (int t = 0; t < 256; t++) {
        // ---- activations + state update + alpha partials (consume C for step t) ----
        float sp0 = 0.0f, sp1 = 0.0f;
#pragma unroll
        for (int ka = 0; ka < 2; ka++)
#pragma unroll
            for (int bh = 0; bh < 2; bh++) {
                int rb = bh << 1;
                float jj = tanha(C[2 * ka][rb]);
                float ii = siga(C[2 * ka][rb + 1]);
                float ff = siga(C[2 * ka + 1][rb]);
                float oo = siga(C[2 * ka + 1][rb + 1]);
                float cn = fmaf(cst[ka][bh], ff, ii * jj);
                cst[ka][bh] = cn;
                float hv = oo * tanha(cn);
                hn[ka][bh] = hv;
                if (bh == 0) sp0 = fmaf(hv, fav[ka], sp0);
                else         sp1 = fmaf(hv, fav[ka], sp1);
            }
        sp0 += __shfl_xor_sync(0xffffffffu, sp0, 1);
        sp0 += __shfl_xor_sync(0xffffffffu, sp0, 2);
        sp1 += __shfl_xor_sync(0xffffffffu, sp1, 1);
        sp1 += __shfl_xor_sync(0xffffffffu, sp1, 2);
        const int spb = spbase + (t & 1) * 128;
        if (t4 == 0) {
            sm[spb + wg * 16 + g]     = sp0;
            sm[spb + wg * 16 + g + 8] = sp1;
        }

        // ---- write h(t) as tf32-rounded floats to ping-pong buffer ----
        float* hw = sm + hbase + (cur ^ 1) * 1088;
#pragma unroll
        for (int ka = 0; ka < 2; ka++) {
            int kk = 8 * wg + 4 * ka + t4;
#pragma unroll
            for (int bh = 0; bh < 2; bh++)
                hw[(g + 8 * bh) * 68 + kk] =
                    __uint_as_float(cvt_tf32(hn[ka][bh]));
        }

        GBAR(gid);  // ONE barrier per step: sp(t) + h(t) visible within group

        // ---- issue next step's GEMM FIRST (alpha runs in its shadow) ----
        if (t < 255) {
            const float xv0 = sm[XS + (t + 1) * 32 + xb0];
            const float xv1 = sm[XS + (t + 1) * 32 + xb0 + 8];
#pragma unroll
            for (int nt = 0; nt < 4; nt++)
#pragma unroll
                for (int r = 0; r < 4; r++) {
                    int gate = ((nt & 1) << 1) + (r & 1);
                    int ka = nt >> 1;
                    C[nt][r] = fmaf((r >> 1) ? xv1 : xv0, Uv[ka][gate], Bv[ka][gate]);
                }
            const float* hb = sm + hbase + (cur ^ 1) * 1088;
#pragma unroll
            for (int kt = 0; kt < 8; kt++) {
                int c0 = kt * 8 + t4;
                unsigned a0 = __float_as_uint(hb[g * 68 + c0]);
                unsigned a1 = __float_as_uint(hb[(g + 8) * 68 + c0]);
                unsigned a2 = __float_as_uint(hb[g * 68 + c0 + 4]);
                unsigned a3 = __float_as_uint(hb[(g + 8) * 68 + c0 + 4]);
#pragma unroll
                for (int nt = 0; nt < 4; nt++)
                    mma8(C[nt], a0, a1, a2, a3, Bhi[kt][nt][0], Bhi[kt][nt][1]);
            }
        }

        // ---- alpha(t): computed redundantly by every warp (in MMA shadow) ----
        {
            const float* spp = sm + spb;
            float sA = FabV, sB = 0.0f;
#pragma unroll
            for (int ww = 0; ww < 8; ww += 2) {
                sA += spp[ww * 16 + bl];
                sB += spp[(ww + 1) * 16 + bl];
            }
            float av = __expf(tanha(sA + sB));
            den += av;
            float av0 = __shfl_sync(0xffffffffu, av, g);
            float av1 = __shfl_sync(0xffffffffu, av, g + 8);
#pragma unroll
            for (int ka = 0; ka < 2; ka++) {
                gacc[ka][0] = fmaf(av0, hn[ka][0], gacc[ka][0]);
                gacc[ka][1] = fmaf(av1, hn[ka][1], gacc[ka][1]);
            }
            if (wg == 0 && lane < 16)
                g_aBuf[(i * 256 + t) * 128 + b0g + lane] = av;
        }

        cur ^= 1;
    }

    // ---- finalize denominators ----
    if (wg == 0 && lane < 16) {
        sm[INVF + gid * 16 + lane] = __fdividef(1.0f, den);
        g_denBuf[i * 128 + b0g + lane] = den;
    }
    GBAR(gid);

    // ---- epilogue: write g_n and h_T ----
    {
        float inv0 = sm[INVF + gid * 16 + g];
        float inv1 = sm[INVF + gid * 16 + g + 8];
#pragma unroll
        for (int ka = 0; ka < 2; ka++) {
            int kk = 8 * wg + 4 * ka + t4;
            int bg0 = b0g + g, bg1 = b0g + g + 8;
            g_gBuf[(bg0 * 32 + i) * 64 + kk]  = gacc[ka][0] * inv0;
            g_gBuf[(bg1 * 32 + i) * 64 + kk]  = gacc[ka][1] * inv1;
            g_hTBuf[(bg0 * 32 + i) * 64 + kk] = hn[ka][0];
            g_hTBuf[(bg1 * 32 + i) * 64 + kk] = hn[ka][1];
        }
    }
}

// ===================== Kernel 2: normalize alphas into [B,T,D] =====================
__global__ void alpha_kernel(float* __restrict__ out) {
    int idx = blockIdx.x * 256 + threadIdx.x;  // 0 .. 1048575
    int b = idx >> 13;
    int r = idx & 8191;
    int t = r >> 5;
    int i = r & 31;
    float a = g_aBuf[(i * 256 + t) * 128 + b];
    float d = g_denBuf[i * 128 + b];
    out[128 + idx] = __fdividef(a, d);
}

// ===================== Kernel 3: output head =====================
__global__ void head_kernel(float* __restrict__ out,
                            const float* __restrict__ Phi_w, const float* __restrict__ Phi_b,
                            const float* __restrict__ Fbw, const float* __restrict__ Fbb) {
    int b = blockIdx.x;
    int i = threadIdx.x;
    const float* gp = g_gBuf + (b * 32 + i) * 64;
    const float* hp = g_hTBuf + (b * 32 + i) * 64;
    float mu = Phi_b[0];
    float bs = Fbb[0];
#pragma unroll 8
    for (int kk = 0; kk < 64; kk++) {
        float gv = gp[kk], hv = hp[kk];
        mu = fmaf(gv, Phi_w[kk], mu);
        mu = fmaf(hv, Phi_w[64 + kk], mu);
        bs = fmaf(gv, Fbw[kk], bs);
        bs = fmaf(hv, Fbw[64 + kk], bs);
    }
    float e = __expf(tanha(bs));
    float se = e, sem = e * mu;
#pragma unroll
    for (int off = 16; off; off >>= 1) {
        se  += __shfl_xor_sync(0xffffffffu, se, off);
        sem += __shfl_xor_sync(0xffffffffu, sem, off);
    }
    out[128 + 1048576 + b * 32 + i] = __fdividef(e, se);  // betas
    if (i == 0) out[b] = __fdividef(sem, se);             // mean
}

// ===================== launch =====================
extern "C" void kernel_launch(void* const* d_in, const int* in_sizes, int n_in,
                              void* d_out, int out_size) {
    const float* x   = (const float*)d_in[0];
    const float* Uj  = (const float*)d_in[1];
    const float* Ui_ = (const float*)d_in[2];
    const float* Uf  = (const float*)d_in[3];
    const float* Uo  = (const float*)d_in[4];
    const float* Wj  = (const float*)d_in[5];
    const float* Wi_ = (const float*)d_in[6];
    const float* Wf  = (const float*)d_in[7];
    const float* Wo  = (const float*)d_in[8];
    const float* bj  = (const float*)d_in[9];
    const float* bi_ = (const float*)d_in[10];
    const float* bf  = (const float*)d_in[11];
    const float* bo  = (const float*)d_in[12];
    const float* Fa  = (const float*)d_in[13];
    const float* Fab = (const float*)d_in[14];
    const float* Fbw = (const float*)d_in[15];
    const float* Fbb = (const float*)d_in[16];
    const float* Pw  = (const float*)d_in[17];
    const float* Pb  = (const float*)d_in[18];
    float* out = (float*)d_out;

    size_t smem = SMTOT * sizeof(float);  // ~52 KB
    cudaFuncSetAttribute(lstm_kernel, cudaFuncAttributeMaxDynamicSharedMemorySize, (int)smem);

    lstm_kernel<<<dim3(32, 4), 512, smem>>>(x, Uj, Ui_, Uf, Uo, Wj, Wi_, Wf, Wo,
                                            bj, bi_, bf, bo, Fa, Fab);
    alpha_kernel<<<4096, 256>>>(out);
    head_kernel<<<128, 32>>>(out, Pw, Pb, Fbw, Fbb);
}

// round 16
// speedup vs baseline: 1.0669x; 1.0669x over previous
#include <cuda_runtime.h>

// Problem constants
#define B_DIM 128
#define T_DIM 256
#define D_DIM 32
#define N_DIM 64

// Scratch (device globals: no allocation allowed)
__device__ float g_aBuf[D_DIM * T_DIM * B_DIM];   // [i][t][b] unnormalized alphas
__device__ float g_denBuf[D_DIM * B_DIM];         // [i][b]
__device__ float g_gBuf[B_DIM * D_DIM * N_DIM];   // [b][i][k] g_n (normalized)
__device__ float g_hTBuf[B_DIM * D_DIM * N_DIM];  // [b][i][k] h_T

// ---------------- math helpers ----------------
static __device__ __forceinline__ float tanha(float x) {
    float y;
    asm("tanh.approx.f32 %0, %1;" : "=f"(y) : "f"(x));
    return y;
}
static __device__ __forceinline__ float siga(float x) {
    return fmaf(tanha(0.5f * x), 0.5f, 0.5f);
}
static __device__ __forceinline__ unsigned cvt_tf32(float x) {
    unsigned r;
    asm("cvt.rna.tf32.f32 %0, %1;" : "=r"(r) : "f"(x));
    return r;
}
// m16n8k8 tf32 MMA, C += A*B  (A row-major frag, B col-major frag)
static __device__ __forceinline__ void mma8(float* C,
                                            unsigned a0, unsigned a1,
                                            unsigned a2, unsigned a3,
                                            unsigned b0, unsigned b1) {
    asm("mma.sync.aligned.m16n8k8.row.col.f32.tf32.tf32.f32 "
        "{%0,%1,%2,%3}, {%4,%5,%6,%7}, {%8,%9}, {%0,%1,%2,%3};"
        : "+f"(C[0]), "+f"(C[1]), "+f"(C[2]), "+f"(C[3])
        : "r"(a0), "r"(a1), "r"(a2), "r"(a3), "r"(b0), "r"(b1));
}
#define GBAR(gid) asm volatile("bar.sync %0, 256;" :: "r"((gid) + 1) : "memory")

// ---------------- shared memory layout (float offsets) ----------------
// x: [t][32 b].  h per group: 2 buffers x [16 rows][stride 68] single tf32 floats.
// sp per group: 2 buffers (t&1) x [8 w][16 b].
#define XS   0       // 8192
#define HBF  8192    // 2 groups * 2 * 1088 = 4352
#define SPF  12544   // 2 groups * 2 * 128 = 512
#define INVF 13056   // 2 * 16 = 32
#define SMTOT 13088  // floats -> 52352 bytes

// ===================== Kernel 1: fused LSTM via single-pass TF32 mma.sync =====================
// grid = (32 i, 4 b-chunks), block = 512 = 2 groups x 8 warps; ONE barrier per step.
// R10 loop ordering (verified fastest). Group 1 takes a one-time ~1000-cycle
// stagger (dependent-FMA delay chain, no clock64) after the last full-CTA
// barrier so the two groups run anti-phased: group 0's MMA phase overlaps
// group 1's activation/alpha phase on the same SMSPs.
// Group gid handles b rows [16*gid, 16*gid+16) (M=16).
// Warp wg owns k in [8wg, 8wg+8): nt0=k(0..3)x(j,i), nt1=k(0..3)x(f,o),
//                                 nt2=k(4..7)x(j,i), nt3=k(4..7)x(f,o).
// Lane (g=lane>>2, t4=lane&3): C cells = b rows {g, g+8} x k {8wg+t4, 8wg+4+t4} x 4 gates.
__global__ void __launch_bounds__(512, 1)
lstm_kernel(const float* __restrict__ x,
            const float* __restrict__ Uj, const float* __restrict__ Ui_,
            const float* __restrict__ Uf, const float* __restrict__ Uo,
            const float* __restrict__ Wj, const float* __restrict__ Wi_,
            const float* __restrict__ Wf, const float* __restrict__ Wo,
            const float* __restrict__ bj, const float* __restrict__ bi_,
            const float* __restrict__ bf, const float* __restrict__ bo,
            const float* __restrict__ Fa, const float* __restrict__ Fab) {
    extern __shared__ float sm[];
    const int tid  = threadIdx.x;
    const int gid  = tid >> 8;            // group 0/1
    const int wg   = (tid >> 5) & 7;      // warp in group
    const int lane = tid & 31;
    const int g    = lane >> 2;
    const int t4   = lane & 3;
    const int bl   = lane & 15;           // b-row for alpha compute
    const int i    = blockIdx.x;
    const int b0g  = (blockIdx.y << 5) + (gid << 4);

    // ---- cooperative smem init (full CTA) ----
    for (int idx = tid; idx < 4352; idx += 512) sm[HBF + idx] = 0.0f;
    {
        const int cb0 = blockIdx.y << 5;
        for (int idx = tid; idx < 8192; idx += 512) {
            int tt = idx >> 5, blx = idx & 31;
            sm[XS + idx] = x[((cb0 + blx) * 256 + tt) * 32 + i];
        }
    }

    // ---- stationary B (weight) fragments, tf32 (exact truncation of W) ----
    unsigned Bhi[8][4][2];
    {
        const float* WgP[4] = {Wj, Wi_, Wf, Wo};
#pragma unroll
        for (int kt = 0; kt < 8; kt++)
#pragma unroll
            for (int nt = 0; nt < 4; nt++) {
                int kB = 8 * wg + ((nt >> 1) << 2) + (g >> 1);
                const float* Wp = WgP[((nt & 1) << 1) + (g & 1)];
#pragma unroll
                for (int r = 0; r < 2; r++) {
                    int j = kt * 8 + t4 + 4 * r;
                    Bhi[kt][nt][r] = cvt_tf32(Wp[(j * 32 + i) * 64 + kB]);
                }
            }
    }

    // ---- per-lane constants: 2 k-values x 4 gates ----
    float Uv[2][4], Bv[2][4], fav[2];
    {
        const float* Ug[4] = {Uj, Ui_, Uf, Uo};
        const float* Bg[4] = {bj, bi_, bf, bo};
#pragma unroll
        for (int ka = 0; ka < 2; ka++) {
            int kk = 8 * wg + 4 * ka + t4;
#pragma unroll
            for (int gg = 0; gg < 4; gg++) {
                Uv[ka][gg] = Ug[gg][i * 64 + kk];
                Bv[ka][gg] = Bg[gg][i * 64 + kk];
            }
            fav[ka] = Fa[kk * 32 + i];
        }
    }
    const float FabV = Fab[i];

    // ---- state ----
    float cst[2][2], gacc[2][2], hn[2][2];
#pragma unroll
    for (int ka = 0; ka < 2; ka++)
#pragma unroll
        for (int bh = 0; bh < 2; bh++) {
            cst[ka][bh] = 0.0f; gacc[ka][bh] = 0.0f; hn[ka][bh] = 0.0f;
        }
    float den = 0.0f;  // per-lane, b = bl (redundant across warps)

    __syncthreads();  // LAST full-CTA barrier: groups are independent after this

    // ---- one-time stagger: group 1 runs a ~1024-cycle dependent-FMA delay ----
    // v converges toward 0.5 from 1.0; the guard below is never taken, but the
    // compiler cannot prove it, so the chain (256 serial FMAs x 4 cyc) survives.
    if (gid == 1) {
        float v = 1.0f;
#pragma unroll 1
        for (int d = 0; d < 256; d++) v = fmaf(v, 0.5f, 0.25f);
        if (v < -1e30f) sm[XS] = v;  // never true
    }

    int cur = 0;
    const int hbase  = HBF + gid * 2176;
    const int spbase = SPF + gid * 256;
    const int xb0    = (gid << 4) + g;

    for (int t = 0; t < 256; t++) {
        // ---- C init = bias + x*U ----
        const float xv0 = sm[XS + t * 32 + xb0];
        const float xv1 = sm[XS + t * 32 + xb0 + 8];
        float C[4][4];
#pragma unroll
        for (int nt = 0; nt < 4; nt++)
#pragma unroll
            for (int r = 0; r < 4; r++) {
                int gate = ((nt & 1) << 1) + (r & 1);
                int ka = nt >> 1;
                C[nt][r] = fmaf((r >> 1) ? xv1 : xv0, Uv[ka][gate], Bv[ka][gate]);
            }

        // ---- MMA: C += A_hi * B  (single tf32 pass) ----
        const float* hb = sm + hbase + cur * 1088;
#pragma unroll
        for (int kt = 0; kt < 8; kt++) {
            int c0 = kt * 8 + t4;
            unsigned a0 = __float_as_uint(hb[g * 68 + c0]);
            unsigned a1 = __float_as_uint(hb[(g + 8) * 68 + c0]);
            unsigned a2 = __float_as_uint(hb[g * 68 + c0 + 4]);
            unsigned a3 = __float_as_uint(hb[(g + 8) * 68 + c0 + 4]);
#pragma unroll
            for (int nt = 0; nt < 4; nt++)
                mma8(C[nt], a0, a1, a2, a3, Bhi[kt][nt][0], Bhi[kt][nt][1]);
        }

        // ---- activations + state update + alpha partials ----
        float sp0 = 0.0f, sp1 = 0.0f;
#pragma unroll
        for (int ka = 0; ka < 2; ka++)
#pragma unroll
            for (int bh = 0; bh < 2; bh++) {
                int rb = bh << 1;
                float jj = tanha(C[2 * ka][rb]);
                float ii = siga(C[2 * ka][rb + 1]);
                float ff = siga(C[2 * ka + 1][rb]);
                float oo = siga(C[2 * ka + 1][rb + 1]);
                float cn = fmaf(cst[ka][bh], ff, ii * jj);
                cst[ka][bh] = cn;
                float hv = oo * tanha(cn);
                hn[ka][bh] = hv;
                if (bh == 0) sp0 = fmaf(hv, fav[ka], sp0);
                else         sp1 = fmaf(hv, fav[ka], sp1);
            }
        sp0 += __shfl_xor_sync(0xffffffffu, sp0, 1);
        sp0 += __shfl_xor_sync(0xffffffffu, sp0, 2);
        sp1 += __shfl_xor_sync(0xffffffffu, sp1, 1);
        sp1 += __shfl_xor_sync(0xffffffffu, sp1, 2);
        const int spb = spbase + (t & 1) * 128;
        if (t4 == 0) {
            sm[spb + wg * 16 + g]     = sp0;
            sm[spb + wg * 16 + g + 8] = sp1;
        }

        // ---- write h(t) as tf32-rounded floats to ping-pong buffer ----
        float* hw = sm + hbase + (cur ^ 1) * 1088;
#pragma unroll
        for (int ka = 0; ka < 2; ka++) {
            int kk = 8 * wg + 4 * ka + t4;
#pragma unroll
            for (int bh = 0; bh < 2; bh++)
                hw[(g + 8 * bh) * 68 + kk] =
                    __uint_as_float(cvt_tf32(hn[ka][bh]));
        }

        GBAR(gid);  // ONE barrier per step: sp(t) + h(t) visible within group

        // ---- alpha(t): computed redundantly by every warp (fully parallel) ----
        {
            const float* spp = sm + spb;
            float sA = FabV, sB = 0.0f;
#pragma unroll
            for (int ww = 0; ww < 8; ww += 2) {
                sA += spp[ww * 16 + bl];
                sB += spp[(ww + 1) * 16 + bl];
            }
            float av = __expf(tanha(sA + sB));
            den += av;
            float av0 = __shfl_sync(0xffffffffu, av, g);
            float av1 = __shfl_sync(0xffffffffu, av, g + 8);
#pragma unroll
            for (int ka = 0; ka < 2; ka++) {
                gacc[ka][0] = fmaf(av0, hn[ka][0], gacc[ka][0]);
                gacc[ka][1] = fmaf(av1, hn[ka][1], gacc[ka][1]);
            }
            if (wg == 0 && lane < 16)
                g_aBuf[(i * 256 + t) * 128 + b0g + lane] = av;
        }

        cur ^= 1;
    }

    // ---- finalize denominators ----
    if (wg == 0 && lane < 16) {
        sm[INVF + gid * 16 + lane] = __fdividef(1.0f, den);
        g_denBuf[i * 128 + b0g + lane] = den;
    }
    GBAR(gid);

    // ---- epilogue: write g_n and h_T ----
    {
        float inv0 = sm[INVF + gid * 16 + g];
        float inv1 = sm[INVF + gid * 16 + g + 8];
#pragma unroll
        for (int ka = 0; ka < 2; ka++) {
            int kk = 8 * wg + 4 * ka + t4;
            int bg0 = b0g + g, bg1 = b0g + g + 8;
            g_gBuf[(bg0 * 32 + i) * 64 + kk]  = gacc[ka][0] * inv0;
            g_gBuf[(bg1 * 32 + i) * 64 + kk]  = gacc[ka][1] * inv1;
            g_hTBuf[(bg0 * 32 + i) * 64 + kk] = hn[ka][0];
            g_hTBuf[(bg1 * 32 + i) * 64 + kk] = hn[ka][1];
        }
    }
}

// ===================== Kernel 2: normalize alphas into [B,T,D] =====================
__global__ void alpha_kernel(float* __restrict__ out) {
    int idx = blockIdx.x * 256 + threadIdx.x;  // 0 .. 1048575
    int b = idx >> 13;
    int r = idx & 8191;
    int t = r >> 5;
    int i = r & 31;
    float a = g_aBuf[(i * 256 + t) * 128 + b];
    float d = g_denBuf[i * 128 + b];
    out[128 + idx] = __fdividef(a, d);
}

// ===================== Kernel 3: output head =====================
__global__ void head_kernel(float* __restrict__ out,
                            const float* __restrict__ Phi_w, const float* __restrict__ Phi_b,
                            const float* __restrict__ Fbw, const float* __restrict__ Fbb) {
    int b = blockIdx.x;
    int i = threadIdx.x;
    const float* gp = g_gBuf + (b * 32 + i) * 64;
    const float* hp = g_hTBuf + (b * 32 + i) * 64;
    float mu = Phi_b[0];
    float bs = Fbb[0];
#pragma unroll 8
    for (int kk = 0; kk < 64; kk++) {
        float gv = gp[kk], hv = hp[kk];
        mu = fmaf(gv, Phi_w[kk], mu);
        mu = fmaf(hv, Phi_w[64 + kk], mu);
        bs = fmaf(gv, Fbw[kk], bs);
        bs = fmaf(hv, Fbw[64 + kk], bs);
    }
    float e = __expf(tanha(bs));
    float se = e, sem = e * mu;
#pragma unroll
    for (int off = 16; off; off >>= 1) {
        se  += __shfl_xor_sync(0xffffffffu, se, off);
        sem += __shfl_xor_sync(0xffffffffu, sem, off);
    }
    out[128 + 1048576 + b * 32 + i] = __fdividef(e, se);  // betas
    if (i == 0) out[b] = __fdividef(sem, se);             // mean
}

// ===================== launch =====================
extern "C" void kernel_launch(void* const* d_in, const int* in_sizes, int n_in,
                              void* d_out, int out_size) {
    const float* x   = (const float*)d_in[0];
    const float* Uj  = (const float*)d_in[1];
    const float* Ui_ = (const float*)d_in[2];
    const float* Uf  = (const float*)d_in[3];
    const float* Uo  = (const float*)d_in[4];
    const float* Wj  = (const float*)d_in[5];
    const float* Wi_ = (const float*)d_in[6];
    const float* Wf  = (const float*)d_in[7];
    const float* Wo  = (const float*)d_in[8];
    const float* bj  = (const float*)d_in[9];
    const float* bi_ = (const float*)d_in[10];
    const float* bf  = (const float*)d_in[11];
    const float* bo  = (const float*)d_in[12];
    const float* Fa  = (const float*)d_in[13];
    const float* Fab = (const float*)d_in[14];
    const float* Fbw = (const float*)d_in[15];
    const float* Fbb = (const float*)d_in[16];
    const float* Pw  = (const float*)d_in[17];
    const float* Pb  = (const float*)d_in[18];
    float* out = (float*)d_out;

    size_t smem = SMTOT * sizeof(float);  // ~52 KB
    cudaFuncSetAttribute(lstm_kernel, cudaFuncAttributeMaxDynamicSharedMemorySize, (int)smem);

    lstm_kernel<<<dim3(32, 4), 512, smem>>>(x, Uj, Ui_, Uf, Uo, Wj, Wi_, Wf, Wo,
                                            bj, bi_, bf, bo, Fa, Fab);
    alpha_kernel<<<4096, 256>>>(out);
    head_kernel<<<128, 32>>>(out, Pw, Pb, Fbw, Fbb);
}

// round 17
// speedup vs baseline: 1.3822x; 1.2956x over previous
#include <cuda_runtime.h>
#include <cuda_bf16.h>

// Problem constants
#define B_DIM 128
#define T_DIM 256
#define D_DIM 32
#define N_DIM 64

// Scratch (device globals: no allocation allowed)
__device__ float g_aBuf[D_DIM * T_DIM * B_DIM];   // [i][t][b] unnormalized alphas
__device__ float g_denBuf[D_DIM * B_DIM];         // [i][b]
__device__ float g_gBuf[B_DIM * D_DIM * N_DIM];   // [b][i][k] g_n (normalized)
__device__ float g_hTBuf[B_DIM * D_DIM * N_DIM];  // [b][i][k] h_T

// ---------------- math helpers ----------------
static __device__ __forceinline__ float tanha(float x) {
    float y;
    asm("tanh.approx.f32 %0, %1;" : "=f"(y) : "f"(x));
    return y;
}
static __device__ __forceinline__ float siga(float x) {
    return fmaf(tanha(0.5f * x), 0.5f, 0.5f);
}
// pack two floats into bf16x2: lower half = lo, upper half = hi
static __device__ __forceinline__ unsigned pack_bf2(float lo, float hi) {
    unsigned r;
    asm("cvt.rn.bf16x2.f32 %0, %1, %2;" : "=r"(r) : "f"(hi), "f"(lo));
    return r;
}
// m16n8k16 bf16 MMA, C += A*B  (A row-major frag, B col-major frag)
static __device__ __forceinline__ void mma16(float* C,
                                             unsigned a0, unsigned a1,
                                             unsigned a2, unsigned a3,
                                             unsigned b0, unsigned b1) {
    asm("mma.sync.aligned.m16n8k16.row.col.f32.bf16.bf16.f32 "
        "{%0,%1,%2,%3}, {%4,%5,%6,%7}, {%8,%9}, {%0,%1,%2,%3};"
        : "+f"(C[0]), "+f"(C[1]), "+f"(C[2]), "+f"(C[3])
        : "r"(a0), "r"(a1), "r"(a2), "r"(a3), "r"(b0), "r"(b1));
}
#define GBAR(gid) asm volatile("bar.sync %0, 256;" :: "r"((gid) + 1) : "memory")

// ---------------- shared memory layout (float/uint offsets) ----------------
// x: [t][32 b] floats.
// h per group: 2 buffers x [16 rows][36 uints] of packed bf16 pairs (72 bf16/row, 64 used).
// sp per group: 2 buffers (t&1) x [8 w][16 b].
#define XS   0       // 8192 floats
#define HBF  8192    // 2 groups * 2 * 576 = 2304 words
#define SPF  10496   // 2 groups * 2 * 128 = 512
#define INVF 11008   // 2 * 16 = 32
#define SMTOT 11040  // words -> 44160 bytes

// ===================== Kernel 1: fused LSTM via bf16 m16n8k16 mma.sync =====================
// grid = (32 i, 4 b-chunks), block = 512 = 2 groups x 8 warps; ONE barrier per step.
// R10 loop ordering (verified fastest). Per group step GEMM:
//   C[16b x 256gk] = bf16(h)[16b x 64j] * bf16(W')[64j x 256gk], fp32 accum.
// Warp wg owns k in [8wg, 8wg+8): nt0=k(0..3)x(j,i), nt1=k(0..3)x(f,o),
//                                 nt2=k(4..7)x(j,i), nt3=k(4..7)x(f,o).
// Lane (g=lane>>2, t4=lane&3): C cells = b rows {g, g+8} x k {8wg+t4, 8wg+4+t4} x 4 gates.
// kt = 0..3 (k16 per MMA): A frag words = hb[row][kt*8 + t4] and [kt*8 + t4 + 4].
__global__ void __launch_bounds__(512, 1)
lstm_kernel(const float* __restrict__ x,
            const float* __restrict__ Uj, const float* __restrict__ Ui_,
            const float* __restrict__ Uf, const float* __restrict__ Uo,
            const float* __restrict__ Wj, const float* __restrict__ Wi_,
            const float* __restrict__ Wf, const float* __restrict__ Wo,
            const float* __restrict__ bj, const float* __restrict__ bi_,
            const float* __restrict__ bf, const float* __restrict__ bo,
            const float* __restrict__ Fa, const float* __restrict__ Fab) {
    extern __shared__ float sm[];
    const int tid  = threadIdx.x;
    const int gid  = tid >> 8;            // group 0/1
    const int wg   = (tid >> 5) & 7;      // warp in group
    const int lane = tid & 31;
    const int g    = lane >> 2;
    const int t4   = lane & 3;
    const int bl   = lane & 15;           // b-row for alpha compute
    const int i    = blockIdx.x;
    const int b0g  = (blockIdx.y << 5) + (gid << 4);

    // ---- cooperative smem init (full CTA) ----
    for (int idx = tid; idx < 2304; idx += 512) sm[HBF + idx] = 0.0f;  // zero bf16 h bufs
    {
        const int cb0 = blockIdx.y << 5;
        for (int idx = tid; idx < 8192; idx += 512) {
            int tt = idx >> 5, blx = idx & 31;
            sm[XS + idx] = x[((cb0 + blx) * 256 + tt) * 32 + i];
        }
    }

    // ---- stationary B (weight) fragments, packed bf16 pairs along j ----
    // Bpk[kt][nt][r]: lo = W[j0][col], hi = W[j0+1][col], j0 = kt*16 + 2*t4 + 8*r.
    // col g -> k = 8wg + 4*(nt>>1) + (g>>1), gate = 2*(nt&1) + (g&1).
    unsigned Bpk[4][4][2];
    {
        const float* WgP[4] = {Wj, Wi_, Wf, Wo};
#pragma unroll
        for (int kt = 0; kt < 4; kt++)
#pragma unroll
            for (int nt = 0; nt < 4; nt++) {
                int kB = 8 * wg + ((nt >> 1) << 2) + (g >> 1);
                const float* Wp = WgP[((nt & 1) << 1) + (g & 1)];
#pragma unroll
                for (int r = 0; r < 2; r++) {
                    int j0 = kt * 16 + 2 * t4 + 8 * r;
                    float w0 = Wp[(j0 * 32 + i) * 64 + kB];
                    float w1 = Wp[((j0 + 1) * 32 + i) * 64 + kB];
                    Bpk[kt][nt][r] = pack_bf2(w0, w1);
                }
            }
    }

    // ---- per-lane constants: 2 k-values x 4 gates ----
    float Uv[2][4], Bv[2][4], fav[2];
    {
        const float* Ug[4] = {Uj, Ui_, Uf, Uo};
        const float* Bg[4] = {bj, bi_, bf, bo};
#pragma unroll
        for (int ka = 0; ka < 2; ka++) {
            int kk = 8 * wg + 4 * ka + t4;
#pragma unroll
            for (int gg = 0; gg < 4; gg++) {
                Uv[ka][gg] = Ug[gg][i * 64 + kk];
                Bv[ka][gg] = Bg[gg][i * 64 + kk];
            }
            fav[ka] = Fa[kk * 32 + i];
        }
    }
    const float FabV = Fab[i];

    // ---- state ----
    float cst[2][2], gacc[2][2], hn[2][2];
#pragma unroll
    for (int ka = 0; ka < 2; ka++)
#pragma unroll
        for (int bh = 0; bh < 2; bh++) {
            cst[ka][bh] = 0.0f; gacc[ka][bh] = 0.0f; hn[ka][bh] = 0.0f;
        }
    float den = 0.0f;  // per-lane, b = bl (redundant across warps)

    __syncthreads();
    int cur = 0;
    const int hbase  = HBF + gid * 1152;  // uint words
    const int spbase = SPF + gid * 256;
    const int xb0    = (gid << 4) + g;

    for (int t = 0; t < 256; t++) {
        // ---- C init = bias + x*U ----
        const float xv0 = sm[XS + t * 32 + xb0];
        const float xv1 = sm[XS + t * 32 + xb0 + 8];
        float C[4][4];
#pragma unroll
        for (int nt = 0; nt < 4; nt++)
#pragma unroll
            for (int r = 0; r < 4; r++) {
                int gate = ((nt & 1) << 1) + (r & 1);
                int ka = nt >> 1;
                C[nt][r] = fmaf((r >> 1) ? xv1 : xv0, Uv[ka][gate], Bv[ka][gate]);
            }

        // ---- MMA: C += bf16(h) * bf16(W), k16 per step, 16 MMAs ----
        const unsigned* hb = (const unsigned*)(sm + hbase + cur * 576);
#pragma unroll
        for (int kt = 0; kt < 4; kt++) {
            int c0 = kt * 8 + t4;
            unsigned a0 = hb[g * 36 + c0];
            unsigned a1 = hb[(g + 8) * 36 + c0];
            unsigned a2 = hb[g * 36 + c0 + 4];
            unsigned a3 = hb[(g + 8) * 36 + c0 + 4];
#pragma unroll
            for (int nt = 0; nt < 4; nt++)
                mma16(C[nt], a0, a1, a2, a3, Bpk[kt][nt][0], Bpk[kt][nt][1]);
        }

        // ---- activations + state update + alpha partials ----
        float sp0 = 0.0f, sp1 = 0.0f;
#pragma unroll
        for (int ka = 0; ka < 2; ka++)
#pragma unroll
            for (int bh = 0; bh < 2; bh++) {
                int rb = bh << 1;
                float jj = tanha(C[2 * ka][rb]);
                float ii = siga(C[2 * ka][rb + 1]);
                float ff = siga(C[2 * ka + 1][rb]);
                float oo = siga(C[2 * ka + 1][rb + 1]);
                float cn = fmaf(cst[ka][bh], ff, ii * jj);
                cst[ka][bh] = cn;
                float hv = oo * tanha(cn);
                hn[ka][bh] = hv;
                if (bh == 0) sp0 = fmaf(hv, fav[ka], sp0);
                else         sp1 = fmaf(hv, fav[ka], sp1);
            }
        sp0 += __shfl_xor_sync(0xffffffffu, sp0, 1);
        sp0 += __shfl_xor_sync(0xffffffffu, sp0, 2);
        sp1 += __shfl_xor_sync(0xffffffffu, sp1, 1);
        sp1 += __shfl_xor_sync(0xffffffffu, sp1, 2);
        const int spb = spbase + (t & 1) * 128;
        if (t4 == 0) {
            sm[spb + wg * 16 + g]     = sp0;
            sm[spb + wg * 16 + g + 8] = sp1;
        }

        // ---- write h(t) as bf16 to ping-pong buffer (72 bf16 per row) ----
        {
            __nv_bfloat16* hw =
                (__nv_bfloat16*)(sm + hbase + (cur ^ 1) * 576);
#pragma unroll
            for (int ka = 0; ka < 2; ka++) {
                int kk = 8 * wg + 4 * ka + t4;
                hw[g * 72 + kk]       = __float2bfloat16(hn[ka][0]);
                hw[(g + 8) * 72 + kk] = __float2bfloat16(hn[ka][1]);
            }
        }

        GBAR(gid);  // ONE barrier per step: sp(t) + h(t) visible within group

        // ---- alpha(t): computed redundantly by every warp (fully parallel) ----
        {
            const float* spp = sm + spb;
            float sA = FabV, sB = 0.0f;
#pragma unroll
            for (int ww = 0; ww < 8; ww += 2) {
                sA += spp[ww * 16 + bl];
                sB += spp[(ww + 1) * 16 + bl];
            }
            float av = __expf(tanha(sA + sB));
            den += av;
            float av0 = __shfl_sync(0xffffffffu, av, g);
            float av1 = __shfl_sync(0xffffffffu, av, g + 8);
#pragma unroll
            for (int ka = 0; ka < 2; ka++) {
                gacc[ka][0] = fmaf(av0, hn[ka][0], gacc[ka][0]);
                gacc[ka][1] = fmaf(av1, hn[ka][1], gacc[ka][1]);
            }
            if (wg == 0 && lane < 16)
                g_aBuf[(i * 256 + t) * 128 + b0g + lane] = av;
        }

        cur ^= 1;
    }

    // ---- finalize denominators ----
    if (wg == 0 && lane < 16) {
        sm[INVF + gid * 16 + lane] = __fdividef(1.0f, den);
        g_denBuf[i * 128 + b0g + lane] = den;
    }
    GBAR(gid);

    // ---- epilogue: write g_n and h_T ----
    {
        float inv0 = sm[INVF + gid * 16 + g];
        float inv1 = sm[INVF + gid * 16 + g + 8];
#pragma unroll
        for (int ka = 0; ka < 2; ka++) {
            int kk = 8 * wg + 4 * ka + t4;
            int bg0 = b0g + g, bg1 = b0g + g + 8;
            g_gBuf[(bg0 * 32 + i) * 64 + kk]  = gacc[ka][0] * inv0;
            g_gBuf[(bg1 * 32 + i) * 64 + kk]  = gacc[ka][1] * inv1;
            g_hTBuf[(bg0 * 32 + i) * 64 + kk] = hn[ka][0];
            g_hTBuf[(bg1 * 32 + i) * 64 + kk] = hn[ka][1];
        }
    }
}

// ===================== Kernel 2: normalize alphas into [B,T,D] =====================
__global__ void alpha_kernel(float* __restrict__ out) {
    int idx = blockIdx.x * 256 + threadIdx.x;  // 0 .. 1048575
    int b = idx >> 13;
    int r = idx & 8191;
    int t = r >> 5;
    int i = r & 31;
    float a = g_aBuf[(i * 256 + t) * 128 + b];
    float d = g_denBuf[i * 128 + b];
    out[128 + idx] = __fdividef(a, d);
}

// ===================== Kernel 3: output head =====================
__global__ void head_kernel(float* __restrict__ out,
                            const float* __restrict__ Phi_w, const float* __restrict__ Phi_b,
                            const float* __restrict__ Fbw, const float* __restrict__ Fbb) {
    int b = blockIdx.x;
    int i = threadIdx.x;
    const float* gp = g_gBuf + (b * 32 + i) * 64;
    const float* hp = g_hTBuf + (b * 32 + i) * 64;
    float mu = Phi_b[0];
    float bs = Fbb[0];
#pragma unroll 8
    for (int kk = 0; kk < 64; kk++) {
        float gv = gp[kk], hv = hp[kk];
        mu = fmaf(gv, Phi_w[kk], mu);
        mu = fmaf(hv, Phi_w[64 + kk], mu);
        bs = fmaf(gv, Fbw[kk], bs);
        bs = fmaf(hv, Fbw[64 + kk], bs);
    }
    float e = __expf(tanha(bs));
    float se = e, sem = e * mu;
#pragma unroll
    for (int off = 16; off; off >>= 1) {
        se  += __shfl_xor_sync(0xffffffffu, se, off);
        sem += __shfl_xor_sync(0xffffffffu, sem, off);
    }
    out[128 + 1048576 + b * 32 + i] = __fdividef(e, se);  // betas
    if (i == 0) out[b] = __fdividef(sem, se);             // mean
}

// ===================== launch =====================
extern "C" void kernel_launch(void* const* d_in, const int* in_sizes, int n_in,
                              void* d_out, int out_size) {
    const float* x   = (const float*)d_in[0];
    const float* Uj  = (const float*)d_in[1];
    const float* Ui_ = (const float*)d_in[2];
    const float* Uf  = (const float*)d_in[3];
    const float* Uo  = (const float*)d_in[4];
    const float* Wj  = (const float*)d_in[5];
    const float* Wi_ = (const float*)d_in[6];
    const float* Wf  = (const float*)d_in[7];
    const float* Wo  = (const float*)d_in[8];
    const float* bj  = (const float*)d_in[9];
    const float* bi_ = (const float*)d_in[10];
    const float* bf  = (const float*)d_in[11];
    const float* bo  = (const float*)d_in[12];
    const float* Fa  = (const float*)d_in[13];
    const float* Fab = (const float*)d_in[14];
    const float* Fbw = (const float*)d_in[15];
    const float* Fbb = (const float*)d_in[16];
    const float* Pw  = (const float*)d_in[17];
    const float* Pb  = (const float*)d_in[18];
    float* out = (float*)d_out;

    size_t smem = SMTOT * sizeof(float);  // ~43 KB
    cudaFuncSetAttribute(lstm_kernel, cudaFuncAttributeMaxDynamicSharedMemorySize, (int)smem);

    lstm_kernel<<<dim3(32, 4), 512, smem>>>(x, Uj, Ui_, Uf, Uo, Wj, Wi_, Wf, Wo,
                                            bj, bi_, bf, bo, Fa, Fab);
    alpha_kernel<<<4096, 256>>>(out);
    head_kernel<<<128, 32>>>(out, Pw, Pb, Fbw, Fbb);
}